// round 4
// baseline (speedup 1.0000x reference)
#include <cuda_runtime.h>

// Problem constants
#define B_TOTAL 65536
#define CN 16
#define CC 16
#define DIM 128
#define VOC 65
#define EPSF 1e-5f

#define NCHUNK 4          // D split into 4 chunks of 32 floats
#define DCH 32
#define NBX 37            // 37 * 4 = 148 CTAs = one per SM (persistent)
#define NTHREADS 512
#define TILE 64           // rows per inner tile (64 row-groups of 8 threads)

// Shared memory layout (in floats):
//   emb_s : CC*VOC*DCH = 16*65*32 = 33280
//   z_s   : TILE*CN    = 1024
//   off_s : TILE*CC    = 1024 (ints)
//   mean_s: 16, inv_s: 16
#define EMB_S_FLOATS (CC * VOC * DCH)          // 33280
#define SMEM_FLOATS  (EMB_S_FLOATS + 1024 + 1024 + 32)
#define SMEM_BYTES   (SMEM_FLOATS * 4)

__global__ __launch_bounds__(NTHREADS, 1)
void embed_att_kernel(const float* __restrict__ x_num,
                      const float* __restrict__ means,
                      const float* __restrict__ stds,
                      const float* __restrict__ lin_W,
                      const float* __restrict__ lin_b,
                      const float* __restrict__ emb,
                      const int*   __restrict__ x_cat,
                      float*       __restrict__ out)
{
    extern __shared__ float smem[];
    float* emb_s  = smem;                                   // 33280 floats
    float* z_s    = smem + EMB_S_FLOATS;                    // 1024
    int*   off_s  = (int*)(smem + EMB_S_FLOATS + 1024);     // 1024 ints
    float* mean_s = smem + EMB_S_FLOATS + 2048;             // 16
    float* inv_s  = mean_s + CN;                            // 16

    const int tid   = threadIdx.x;
    const int chunk = blockIdx.y;
    const int dbase = chunk * DCH;

    // ---- Preload embedding chunk into SMEM (1040 vectors x 32 floats = 8320 float4) ----
    {
        float4* es4 = (float4*)emb_s;
        for (int s = tid; s < CC * VOC * (DCH / 4); s += NTHREADS) {
            int pair = s >> 3;          // (c*VOC + v)
            int qq   = s & 7;           // float4 slot within 32-float chunk
            es4[pair * 8 + qq] =
                *(const float4*)(emb + (size_t)pair * DIM + dbase + qq * 4);
        }
    }
    if (tid < CN) {
        mean_s[tid] = means[tid];
        inv_s[tid]  = 1.0f / (stds[tid] + EPSF);
    }

    // ---- Per-thread register state: W chunk + summed bias ----
    const int q = tid & 7;     // float4 slot (0..7) within 32-float chunk
    const int g = tid >> 3;    // row-group (0..63) within tile
    float4 w[CN];
    float4 bias = make_float4(0.f, 0.f, 0.f, 0.f);
    #pragma unroll
    for (int i = 0; i < CN; i++) {
        w[i] = *(const float4*)(lin_W + i * DIM + dbase + q * 4);
        float4 lb = *(const float4*)(lin_b + i * DIM + dbase + q * 4);
        bias.x += lb.x; bias.y += lb.y; bias.z += lb.z; bias.w += lb.w;
    }
    __syncthreads();

    // ---- Balanced row range for this block ----
    const int bx    = blockIdx.x;
    const int start = (int)(((long long)bx       * B_TOTAL) / NBX);
    const int end   = (int)(((long long)(bx + 1) * B_TOTAL) / NBX);

    const float4* es4 = (const float4*)emb_s;

    for (int tb = start; tb < end; tb += TILE) {
        // ---- Phase 1: compute z + gather offsets for up to 64 rows ----
        for (int s = tid; s < TILE * CN; s += NTHREADS) {
            int r = s >> 4;
            int i = s & 15;
            int b = tb + r;
            if (b < end) {
                float x = x_num[b * CN + i];
                float t = (x - mean_s[i]) * inv_s[i];
                z_s[s]  = 1.0f / (1.0f + __expf(-t));
                int v   = x_cat[b * CC + i];
                off_s[s] = (i * VOC + v) * (DCH / 4);  // float4 index into emb_s
            }
        }
        __syncthreads();

        // ---- Phase 2: each 8-thread group produces one row's 32-float chunk ----
        int b = tb + g;
        if (b < end) {
            float4 acc = bias;
            // categorical gathers: 16 conflict-free LDS.128
            #pragma unroll
            for (int c = 0; c < CC; c++) {
                float4 e = es4[off_s[g * CC + c] + q];
                acc.x += e.x; acc.y += e.y; acc.z += e.z; acc.w += e.w;
            }
            // numeric K=16 mini-GEMM, W in registers, z broadcast from SMEM
            #pragma unroll
            for (int i = 0; i < CN; i++) {
                float zi = z_s[g * CN + i];
                acc.x = fmaf(zi, w[i].x, acc.x);
                acc.y = fmaf(zi, w[i].y, acc.y);
                acc.z = fmaf(zi, w[i].z, acc.z);
                acc.w = fmaf(zi, w[i].w, acc.w);
            }
            *(float4*)(out + (size_t)b * DIM + dbase + q * 4) = acc;
        }
        __syncthreads();
    }
}

extern "C" void kernel_launch(void* const* d_in, const int* in_sizes, int n_in,
                              void* d_out, int out_size)
{
    const float* x_num = (const float*)d_in[0];
    const float* means = (const float*)d_in[1];
    const float* stds  = (const float*)d_in[2];
    const float* lin_W = (const float*)d_in[3];
    const float* lin_b = (const float*)d_in[4];
    const float* emb   = (const float*)d_in[5];
    const int*   x_cat = (const int*)d_in[6];
    float* out = (float*)d_out;

    cudaFuncSetAttribute(embed_att_kernel,
                         cudaFuncAttributeMaxDynamicSharedMemorySize, SMEM_BYTES);

    dim3 grid(NBX, NCHUNK);
    embed_att_kernel<<<grid, NTHREADS, SMEM_BYTES>>>(
        x_num, means, stds, lin_W, lin_b, emb, x_cat, out);
}

// round 5
// speedup vs baseline: 1.7335x; 1.7335x over previous
#include <cuda_runtime.h>
#include <cuda_fp16.h>

// Problem constants
#define B_TOTAL 65536
#define CN 16
#define CC 16
#define DIM 128
#define VOC 65
#define EPSF 1e-5f

// Decomposition: D=128 split into 2 chunks of 64; one warp produces one row-chunk.
#define DCH 64
#define NCHUNK 2
#define NBX 74            // 74 * 2 = 148 CTAs = one per SM
#define NTHREADS 1024
#define NWARPS (NTHREADS / 32)

// Shared memory:
//   emb_s : CC*VOC*DCH halves = 66560 halves = 133120 B  (fp16-staged table chunk)
//   slots : per-warp double-buffered {off, z_bits} x16   = NWARPS*2*16*8 = 8192 B
//   mean/inv : 32 floats
#define EMB_HALVES (CC * VOC * DCH)          // 66560
#define SLOTS_BYTES (NWARPS * 2 * 16 * 8)
#define SMEM_BYTES (EMB_HALVES * 2 + SLOTS_BYTES + 32 * 4)

__global__ __launch_bounds__(NTHREADS, 1)
void embed_att_kernel(const float* __restrict__ x_num,
                      const float* __restrict__ means,
                      const float* __restrict__ stds,
                      const float* __restrict__ lin_W,
                      const float* __restrict__ lin_b,
                      const float* __restrict__ emb,
                      const int*   __restrict__ x_cat,
                      float*       __restrict__ out)
{
    extern __shared__ __align__(16) char smem_raw[];
    __half* emb_s  = (__half*)smem_raw;
    int2*   slots  = (int2*)(smem_raw + EMB_HALVES * 2);
    float*  mean_s = (float*)(smem_raw + EMB_HALVES * 2 + SLOTS_BYTES);
    float*  inv_s  = mean_s + CN;

    const int tid   = threadIdx.x;
    const int lane  = tid & 31;
    const int wrp   = tid >> 5;
    const int chunk = blockIdx.y;
    const int dbase = chunk * DCH;

    // ---- Preload emb chunk into SMEM as fp16 (1040 vectors x 64 halves = 128B each) ----
    for (int s = tid; s < CC * VOC * (DCH / 4); s += NTHREADS) {
        int vec = s >> 4;           // (c*VOC + v),  DCH/4 = 16 float4 per vector
        int jj  = (s & 15) * 4;
        float4 f = *(const float4*)(emb + (size_t)vec * DIM + dbase + jj);
        *(__half2*)(emb_s + vec * DCH + jj)     = __floats2half2_rn(f.x, f.y);
        *(__half2*)(emb_s + vec * DCH + jj + 2) = __floats2half2_rn(f.z, f.w);
    }
    if (tid < CN) {
        mean_s[tid] = means[tid];
        inv_s[tid]  = 1.0f / (stds[tid] + EPSF);
    }

    // ---- Per-thread register state: float2 slice of W, pre-summed bias ----
    const int d = dbase + lane * 2;
    float2 wv[CN];
    float2 bias = make_float2(0.f, 0.f);
    #pragma unroll
    for (int i = 0; i < CN; i++) {
        wv[i] = *(const float2*)(lin_W + i * DIM + d);
        float2 lb = *(const float2*)(lin_b + i * DIM + d);
        bias.x += lb.x; bias.y += lb.y;
    }
    __syncthreads();   // only block-wide barrier in the kernel

    // ---- Balanced row range; each warp walks rows with stride NWARPS ----
    const int bx    = blockIdx.x;
    const int start = (int)(((long long)bx       * B_TOTAL) / NBX);
    const int end   = (int)(((long long)(bx + 1) * B_TOTAL) / NBX);

    int2* myslot = slots + wrp * 32;   // 2 buffers x 16 entries
    const int attr = lane & 15;
    int buf = 0;

    for (int b = start + wrp; b < end; b += NWARPS) {
        // lanes 0..15 produce {gather offset, sigmoid z} for the row's 16 attrs
        float x = __ldg(x_num + b * CN + attr);
        int   v = __ldg(x_cat + b * CC + attr);
        float t = (x - mean_s[attr]) * inv_s[attr];
        float z = 1.0f / (1.0f + __expf(-t));
        int  off = (attr * VOC + v) * DCH;   // half index of 128B-aligned vector
        if (lane < 16)
            myslot[buf * 16 + attr] = make_int2(off, __float_as_int(z));
        __syncwarp();

        float2 acc = bias;
        const int2* sb = myslot + buf * 16;
        #pragma unroll
        for (int c = 0; c < CC; c += 2) {
            int4 p = *(const int4*)(sb + c);   // broadcast LDS.128: {off0,z0,off1,z1}
            // conflict-free gathers: vector spans all 32 banks, lane l -> bank l
            __half2 e0 = *(const __half2*)(emb_s + p.x + lane * 2);
            __half2 e1 = *(const __half2*)(emb_s + p.z + lane * 2);
            float2 ef  = __half22float2(__hadd2(e0, e1));
            acc.x += ef.x; acc.y += ef.y;
            float z0 = __int_as_float(p.y);
            float z1 = __int_as_float(p.w);
            acc.x = fmaf(z0, wv[c].x,     acc.x);
            acc.y = fmaf(z0, wv[c].y,     acc.y);
            acc.x = fmaf(z1, wv[c + 1].x, acc.x);
            acc.y = fmaf(z1, wv[c + 1].y, acc.y);
        }
        *(float2*)(out + (size_t)b * DIM + d) = acc;
        buf ^= 1;
    }
}

extern "C" void kernel_launch(void* const* d_in, const int* in_sizes, int n_in,
                              void* d_out, int out_size)
{
    const float* x_num = (const float*)d_in[0];
    const float* means = (const float*)d_in[1];
    const float* stds  = (const float*)d_in[2];
    const float* lin_W = (const float*)d_in[3];
    const float* lin_b = (const float*)d_in[4];
    const float* emb   = (const float*)d_in[5];
    const int*   x_cat = (const int*)d_in[6];
    float* out = (float*)d_out;

    cudaFuncSetAttribute(embed_att_kernel,
                         cudaFuncAttributeMaxDynamicSharedMemorySize, SMEM_BYTES);

    dim3 grid(NBX, NCHUNK);
    embed_att_kernel<<<grid, NTHREADS, SMEM_BYTES>>>(
        x_num, means, stds, lin_W, lin_b, emb, x_cat, out);
}

// round 6
// speedup vs baseline: 2.2917x; 1.3220x over previous
#include <cuda_runtime.h>
#include <cuda_fp16.h>
#include <string.h>

// Problem constants
#define B_TOTAL 65536
#define CN 16
#define CC 16
#define DIM 128
#define VOC 65
#define EPSF 1e-5f

// Decomposition: D=128 in 2 chunks of 64. One warp handles TWO rows per
// iteration: lanes 0-15 -> row A, lanes 16-31 -> row B. Each lane owns a
// 4-element (8B fp16) slice of its row's 64-wide chunk.
#define DCH 64
#define NCHUNK 2
#define NBX 74            // 74 * 2 = 148 CTAs = one per SM
#define NTHREADS 1024
#define NWARPS 32

// Shared memory:
//   emb_s : CC*VOC*DCH halves = 66560 halves = 133120 B (fp16 table chunk)
//   slots : per-warp, double-buffered: 2 bufs x 16 int4 (A/B interleaved
//           at 16B granularity) = 512 B/warp -> 16384 B
#define EMB_HALVES (CC * VOC * DCH)
#define SLOTS_BYTES (NWARPS * 512)
#define SMEM_BYTES (EMB_HALVES * 2 + SLOTS_BYTES)

__device__ __forceinline__ __half2 u2h2(unsigned u) {
    __half2 h; memcpy(&h, &u, 4); return h;
}

__global__ __launch_bounds__(NTHREADS, 1)
void embed_att_kernel(const float* __restrict__ x_num,
                      const float* __restrict__ means,
                      const float* __restrict__ stds,
                      const float* __restrict__ lin_W,
                      const float* __restrict__ lin_b,
                      const float* __restrict__ emb,
                      const int*   __restrict__ x_cat,
                      float*       __restrict__ out)
{
    extern __shared__ __align__(16) char smem_raw[];
    __half* emb_s = (__half*)smem_raw;
    char*   slots = smem_raw + EMB_HALVES * 2;

    const int tid   = threadIdx.x;
    const int lane  = tid & 31;
    const int wrp   = tid >> 5;
    const int sub   = lane & 15;   // attr index (producer) / 16B slice owner
    const int grp   = lane >> 4;   // 0 = row A, 1 = row B
    const int chunk = blockIdx.y;
    const int dbase = chunk * DCH;

    // ---- Preload emb chunk into SMEM as fp16 (1040 vectors x 128B) ----
    for (int s = tid; s < CC * VOC * (DCH / 4); s += NTHREADS) {
        int vec = s >> 4;
        int jj  = (s & 15) * 4;
        float4 f = *(const float4*)(emb + (size_t)vec * DIM + dbase + jj);
        *(__half2*)(emb_s + vec * DCH + jj)     = __floats2half2_rn(f.x, f.y);
        *(__half2*)(emb_s + vec * DCH + jj + 2) = __floats2half2_rn(f.z, f.w);
    }

    // ---- Per-lane constants ----
    const float invr = 1.0f / (stds[sub] + EPSF);
    const float c0   = -means[sub] * invr;
    const int   voff_base = sub * VOC * DCH;     // half-index base for attr 'sub'

    // W slice (4 floats per attr) as 2x half2; bias pre-summed in fp32
    __half2 wa[CN], wb[CN];
    float4 bias = make_float4(0.f, 0.f, 0.f, 0.f);
    #pragma unroll
    for (int i = 0; i < CN; i++) {
        float4 wf = *(const float4*)(lin_W + i * DIM + dbase + 4 * sub);
        wa[i] = __floats2half2_rn(wf.x, wf.y);
        wb[i] = __floats2half2_rn(wf.z, wf.w);
        float4 lb = *(const float4*)(lin_b + i * DIM + dbase + 4 * sub);
        bias.x += lb.x; bias.y += lb.y; bias.z += lb.z; bias.w += lb.w;
    }
    __syncthreads();

    // ---- Balanced row range ----
    const int bx    = blockIdx.x;
    const int start = (int)(((long long)bx       * B_TOTAL) / NBX);
    const int end   = (int)(((long long)(bx + 1) * B_TOTAL) / NBX);

    char* wslot = slots + wrp * 512;
    const __half* myemb = emb_s + 4 * sub;   // this lane's 8B slice offset
    int buf = 0;

    const __half2 h2z = __float2half2_rn(0.f);

    for (int b = start + wrp * 2; b < end; b += 2 * NWARPS) {
        const int  myrow = b + grp;
        const bool valid = myrow < end;

        // ---- Produce: this lane computes {gather offset, z} for (myrow, sub) ----
        float x = 0.f; int v = 0;
        if (valid) {
            x = __ldg(x_num + myrow * CN + sub);
            v = __ldg(x_cat + myrow * CC + sub);
        }
        float t = fmaf(x, invr, c0);
        float z = __fdividef(1.0f, 1.0f + __expf(-t));
        __half2 zz = __floats2half2_rn(z, z);
        int zb; memcpy(&zb, &zz, 4);
        int off = voff_base + v * DCH;        // half-index of 128B vector
        // slot layout: int4 idx = e4*2 + grp  (A/B interleaved per 16B)
        *(int2*)(wslot + buf * 256 + (sub >> 1) * 32 + grp * 16 + (sub & 1) * 8)
            = make_int2(off, zb);
        __syncwarp();

        // ---- Consume: 8 slot reads x {2 gathers + 2 attrs of numeric} ----
        const int4* sl = (const int4*)(wslot + buf * 256 + grp * 16);
        __half2 g00 = h2z, g01 = h2z, g10 = h2z, g11 = h2z;  // gather chains x pairs
        __half2 n0 = h2z, n1 = h2z;                           // numeric chain
        #pragma unroll
        for (int e4 = 0; e4 < 8; e4++) {
            int4 p = sl[e4 * 2];                              // {off0,z0,off1,z1}
            uint2 q0 = *(const uint2*)(myemb + p.x);          // LDS.64 gather
            uint2 q1 = *(const uint2*)(myemb + p.z);
            __half2 zh0 = u2h2((unsigned)p.y);
            __half2 zh1 = u2h2((unsigned)p.w);
            if (e4 < 4) {
                g00 = __hadd2(g00, u2h2(q0.x)); g01 = __hadd2(g01, u2h2(q0.y));
                g00 = __hadd2(g00, u2h2(q1.x)); g01 = __hadd2(g01, u2h2(q1.y));
            } else {
                g10 = __hadd2(g10, u2h2(q0.x)); g11 = __hadd2(g11, u2h2(q0.y));
                g10 = __hadd2(g10, u2h2(q1.x)); g11 = __hadd2(g11, u2h2(q1.y));
            }
            n0 = __hfma2(zh0, wa[2 * e4],     n0);
            n1 = __hfma2(zh0, wb[2 * e4],     n1);
            n0 = __hfma2(zh1, wa[2 * e4 + 1], n0);
            n1 = __hfma2(zh1, wb[2 * e4 + 1], n1);
        }

        __half2 s0 = __hadd2(__hadd2(g00, g10), n0);
        __half2 s1 = __hadd2(__hadd2(g01, g11), n1);
        float2 f0 = __half22float2(s0);
        float2 f1 = __half22float2(s1);
        if (valid) {
            float4 o = make_float4(bias.x + f0.x, bias.y + f0.y,
                                   bias.z + f1.x, bias.w + f1.y);
            *(float4*)(out + (size_t)myrow * DIM + dbase + 4 * sub) = o;
        }
        buf ^= 1;
    }
}

extern "C" void kernel_launch(void* const* d_in, const int* in_sizes, int n_in,
                              void* d_out, int out_size)
{
    const float* x_num = (const float*)d_in[0];
    const float* means = (const float*)d_in[1];
    const float* stds  = (const float*)d_in[2];
    const float* lin_W = (const float*)d_in[3];
    const float* lin_b = (const float*)d_in[4];
    const float* emb   = (const float*)d_in[5];
    const int*   x_cat = (const int*)d_in[6];
    float* out = (float*)d_out;

    cudaFuncSetAttribute(embed_att_kernel,
                         cudaFuncAttributeMaxDynamicSharedMemorySize, SMEM_BYTES);

    dim3 grid(NBX, NCHUNK);
    embed_att_kernel<<<grid, NTHREADS, SMEM_BYTES>>>(
        x_num, means, stds, lin_W, lin_b, emb, x_cat, out);
}